// round 16
// baseline (speedup 1.0000x reference)
#include <cuda_runtime.h>
#include <cstdint>

#define B 8
#define F 4000
#define S 512
#define E 128
#define H 128

#define SSQ   (S * S)          // 262144
#define BSS   (B * S * S)      // 2097152
#define BSE   (B * S * E)      // 524288

#define KSPLIT 8
#define KCH    (F / KSPLIT)    // 500
#define KB     20              // 25 chunks per block

#define CSTR  9                // padded u64 stride per column (bank-conflict fix)

// ---------------- device scratch (no allocations allowed) ----------------
__device__ float               g_partial[KSPLIT][BSE];   // split-K partials (16 MB)
__device__ unsigned short      g_cand[S][B][8];          // sampled top-8 positions (0xFFFF = no)
__device__ unsigned long long  g_sel[S][B][8];           // final samp per step (prev_idxs)
__device__ unsigned           g_mask32[B][S][16];        // final mask, row-major u32 words

// ---------------- threefry2x32 (exact JAX semantics) ----------------
__device__ __forceinline__ unsigned rotl32(unsigned v, int d) {
    return (v << d) | (v >> (32 - d));
}

__device__ __forceinline__ void threefry2x32(unsigned k0, unsigned k1,
                                             unsigned x0, unsigned x1,
                                             unsigned& o0, unsigned& o1) {
    unsigned ks0 = k0, ks1 = k1, ks2 = k0 ^ k1 ^ 0x1BD11BDAu;
    x0 += ks0; x1 += ks1;
#define TF_RND(r) { x0 += x1; x1 = rotl32(x1, r); x1 ^= x0; }
    TF_RND(13) TF_RND(15) TF_RND(26) TF_RND(6)
    x0 += ks1; x1 += ks2 + 1u;
    TF_RND(17) TF_RND(29) TF_RND(16) TF_RND(24)
    x0 += ks2; x1 += ks0 + 2u;
    TF_RND(13) TF_RND(15) TF_RND(26) TF_RND(6)
    x0 += ks0; x1 += ks1 + 3u;
    TF_RND(17) TF_RND(29) TF_RND(16) TF_RND(24)
    x0 += ks1; x1 += ks2 + 4u;
    TF_RND(13) TF_RND(15) TF_RND(26) TF_RND(6)
    x0 += ks2; x1 += ks0 + 5u;
#undef TF_RND
    o0 = x0; o1 = x1;
}

// ---------------- GEMM1: pre-tanh embedded, split-K, scalar FFMA ----------------
__global__ __launch_bounds__(256, 2)
void k_gemm1(const float* __restrict__ inp, const float* __restrict__ emb) {
    int stile = blockIdx.x;
    int b     = blockIdx.y;
    int ks    = blockIdx.z;
    int t     = threadIdx.x;

    __shared__ float As[KB][128];
    __shared__ float Bs[KB][128];

    int s0 = stile * 128;
    int f0 = ks * KCH;
    int tx = t & 15;
    int ty = t >> 4;

    float acc[8][8];
#pragma unroll
    for (int i = 0; i < 8; ++i)
#pragma unroll
        for (int j = 0; j < 8; ++j) acc[i][j] = 0.f;

    const float* inp_b = inp + (size_t)b * F * S + s0;

    for (int kb = 0; kb < KCH; kb += KB) {
#pragma unroll
        for (int p = 0; p < 10; ++p) {
            int idx = t + 256 * p;
            int row = idx >> 7, col = idx & 127;
            As[row][col] = inp_b[(size_t)(f0 + kb + row) * S + col];
            Bs[row][col] = emb[(size_t)(f0 + kb + row) * E + col];
        }
        __syncthreads();

#pragma unroll
        for (int k = 0; k < KB; ++k) {
            float4 a0 = *reinterpret_cast<const float4*>(&As[k][ty * 8]);
            float4 a1 = *reinterpret_cast<const float4*>(&As[k][ty * 8 + 4]);
            float4 b0 = *reinterpret_cast<const float4*>(&Bs[k][tx * 8]);
            float4 b1 = *reinterpret_cast<const float4*>(&Bs[k][tx * 8 + 4]);
            float av[8] = {a0.x, a0.y, a0.z, a0.w, a1.x, a1.y, a1.z, a1.w};
            float bv[8] = {b0.x, b0.y, b0.z, b0.w, b1.x, b1.y, b1.z, b1.w};
#pragma unroll
            for (int i = 0; i < 8; ++i)
#pragma unroll
                for (int j = 0; j < 8; ++j)
                    acc[i][j] = fmaf(av[i], bv[j], acc[i][j]);
        }
        __syncthreads();
    }

#pragma unroll
    for (int i = 0; i < 8; ++i) {
        float* dst = &g_partial[ks][(size_t)(b * S + s0 + ty * 8 + i) * E + tx * 8];
        *reinterpret_cast<float4*>(dst) =
            make_float4(acc[i][0], acc[i][1], acc[i][2], acc[i][3]);
        *reinterpret_cast<float4*>(dst + 4) =
            make_float4(acc[i][4], acc[i][5], acc[i][6], acc[i][7]);
    }
}

// ---------------- GEMM2 + inline split-K reduce + tanh + sigmoid + clip ---------
__global__ __launch_bounds__(256, 4)
void k_probs(const float* __restrict__ W, const float* __restrict__ bias,
             float* __restrict__ out) {
    int i  = blockIdx.x;
    int t  = threadIdx.x;
    int oq = t & 127;
    int hh = t >> 7;

    __shared__ float es[H][8];
    __shared__ float red[32][128];

#pragma unroll
    for (int p = 0; p < 4; ++p) {
        int idx = t + 256 * p;
        int bb = idx >> 7;
        int h  = idx & 127;
        float ssum = 0.f;
#pragma unroll
        for (int k = 0; k < KSPLIT; ++k)
            ssum += g_partial[k][(size_t)(bb * S + i) * H + h];
        es[h][bb] = tanhf(ssum);
    }
    __syncthreads();

    int o = oq * 4;
    float acc[8][4];
#pragma unroll
    for (int bb = 0; bb < 8; ++bb)
#pragma unroll
        for (int j = 0; j < 4; ++j) acc[bb][j] = 0.f;

    const float* Wp = W + (size_t)i * H * S + (size_t)(hh * 64) * S + o;
#pragma unroll 8
    for (int h = 0; h < 64; ++h) {
        float4 w4 = *reinterpret_cast<const float4*>(Wp + (size_t)h * S);
        float4 eA = *reinterpret_cast<const float4*>(&es[hh * 64 + h][0]);
        float4 eB = *reinterpret_cast<const float4*>(&es[hh * 64 + h][4]);
        float ev[8] = {eA.x, eA.y, eA.z, eA.w, eB.x, eB.y, eB.z, eB.w};
#pragma unroll
        for (int bb = 0; bb < 8; ++bb) {
            acc[bb][0] = fmaf(w4.x, ev[bb], acc[bb][0]);
            acc[bb][1] = fmaf(w4.y, ev[bb], acc[bb][1]);
            acc[bb][2] = fmaf(w4.z, ev[bb], acc[bb][2]);
            acc[bb][3] = fmaf(w4.w, ev[bb], acc[bb][3]);
        }
    }

    if (hh == 1) {
#pragma unroll
        for (int bb = 0; bb < 8; ++bb)
#pragma unroll
            for (int j = 0; j < 4; ++j)
                red[bb * 4 + j][oq] = acc[bb][j];
    }
    __syncthreads();

    if (hh == 0) {
        float4 bi4 = *reinterpret_cast<const float4*>(bias + (size_t)i * S + o);
        float bv[4] = {bi4.x, bi4.y, bi4.z, bi4.w};
#pragma unroll
        for (int bb = 0; bb < 8; ++bb) {
            float v[4];
#pragma unroll
            for (int j = 0; j < 4; ++j) {
                float x = acc[bb][j] + red[bb * 4 + j][oq] + bv[j];
                float p = 1.0f / (1.0f + expf(-x));
                v[j] = fminf(fmaxf(p, 1e-4f), 0.9999f);
            }
            *reinterpret_cast<float4*>(out + (size_t)(bb * S + i) * S + o) =
                make_float4(v[0], v[1], v[2], v[3]);
        }
    }
}

// ---------------- fused top-8 + bernoulli -> candidate position list ------------
__global__ void k_topk_sample(const float* __restrict__ probs) {
    int warp = blockIdx.x * (blockDim.x >> 5) + (threadIdx.x >> 5);  // 0..4095
    int lane = threadIdx.x & 31;
    int b = warp >> 9;
    int t = warp & 511;
    const float* row = probs + (size_t)(b * S + t) * S;

    float v[16];
#pragma unroll
    for (int j = 0; j < 16; ++j) v[j] = row[lane + 32 * j];

    unsigned taken = 0;
    int my_s = 0;

#pragma unroll
    for (int r = 0; r < 8; ++r) {
        float bestv = -1e30f;
        int   besto = 1 << 30;
#pragma unroll
        for (int j = 0; j < 16; ++j) {
            if (!((taken >> j) & 1u)) {
                int o = lane + 32 * j;
                if (v[j] > bestv) { bestv = v[j]; besto = o; }
            }
        }
#pragma unroll
        for (int d = 16; d; d >>= 1) {
            float ov = __shfl_xor_sync(0xFFFFFFFFu, bestv, d);
            int   oo = __shfl_xor_sync(0xFFFFFFFFu, besto, d);
            if (ov > bestv || (ov == bestv && oo < besto)) { bestv = ov; besto = oo; }
        }
        if ((besto & 31) == lane) taken |= 1u << (besto >> 5);
        if (lane == r) my_s = besto;
    }

    if (lane < 8) {
        unsigned kk0, kk1;
        threefry2x32(0u, 42u, 0u, (unsigned)t, kk0, kk1);
        unsigned o0, o1;
        threefry2x32(kk0, kk1, 0u, (unsigned)(b * S + my_s), o0, o1);
        unsigned bits = o0 ^ o1;
        float u = __uint_as_float((bits >> 9) | 0x3f800000u) - 1.0f;
        float p = row[my_s];
        g_cand[t][b][lane] = (u < p) ? (unsigned short)my_s : (unsigned short)0xFFFF;
    }
}

// ---------------- scan v4c: COLUMN-ONLY + stride-9 padding ----------------------
// Identical to the round-10 v4b kernel (best measured: 366us) except colT column
// stride is padded 8 -> 9 u64 (72B): Phase-B per-thread column accesses go from
// 16-way bank conflicts ((tid*16+2w)%32 in {0,16}+2w) to 2-way ((tid*18+2w)%32,
// gcd(18,32)=2). Two barriers per step; race-free by construction.
__global__ __launch_bounds__(256, 1)
void k_scan() {
    int b    = blockIdx.x;
    int tid  = threadIdx.x;
    int lane = tid & 31;
    int w    = lane & 7;          // word this lane computes in Phase A
    int jg   = lane >> 3;         // candidate group: handles jg and jg+4

    __shared__ unsigned long long colT[S * CSTR];  // 36.9KB column-major mask (padded)
    __shared__ ulonglong2         candS[S];        // 8KB candidate lists

    for (int i = tid; i < S * CSTR; i += 256) colT[i] = 0ull;
    for (int i = tid; i < S; i += 256)
        candS[i] = *reinterpret_cast<const ulonglong2*>(&g_cand[i][b][0]);

    unsigned long long c0[8] = {0,0,0,0,0,0,0,0};  // col tid (register mirror)
    unsigned long long c1[8] = {0,0,0,0,0,0,0,0};  // col tid+256
    __syncthreads();

    int a1 = tid + 256;

    for (int t = 0; t < S; ++t) {
        int wt = t >> 6;
        int sb = t & 63;

        // ---- Phase A (replicated in every warp; reads only) ----
        ulonglong2 cd = candS[t];
        int cA = (int)((cd.x >> (16 * jg)) & 0xFFFFull);
        int cB = (int)((cd.y >> (16 * jg)) & 0xFFFFull);

        unsigned long long anc = 0ull, smp = 0ull;
        {
            bool valid = (cA < S) && (cA != t);
            int ci = valid ? cA : 0;
            unsigned long long fw = colT[ci * CSTR + wt];   // filter: bit t
            unsigned long long cv = colT[ci * CSTR + w];    // anc contribution
            bool keep = valid && !((fw >> sb) & 1ull);
            if (keep) {
                anc |= cv;
                if ((ci >> 6) == w) smp |= 1ull << (ci & 63);
            }
        }
        {
            bool valid = (cB < S) && (cB != t);
            int ci = valid ? cB : 0;
            unsigned long long fw = colT[ci * CSTR + wt];
            unsigned long long cv = colT[ci * CSTR + w];
            bool keep = valid && !((fw >> sb) & 1ull);
            if (keep) {
                anc |= cv;
                if ((ci >> 6) == w) smp |= 1ull << (ci & 63);
            }
        }

        // reduce across the 4 candidate groups (lanes w, w+8, w+16, w+24)
        anc |= __shfl_xor_sync(0xFFFFFFFFu, anc, 8);
        anc |= __shfl_xor_sync(0xFFFFFFFFu, anc, 16);
        smp |= __shfl_xor_sync(0xFFFFFFFFu, smp, 8);
        smp |= __shfl_xor_sync(0xFFFFFFFFu, smp, 16);

        unsigned long long cvw = colT[t * CSTR + w] | smp | anc;  // col_vec word w

        unsigned long long cvAll[8];
#pragma unroll
        for (int w2 = 0; w2 < 8; ++w2)
            cvAll[w2] = __shfl_sync(0xFFFFFFFFu, cvw, w2);

        if (tid < 8) g_sel[t][b][tid] = smp;   // lanes 0..7 hold words 0..7

        __syncthreads();   // Phase A reads complete before Phase B writes

        // ---- Phase B: column updates only (writes) ----
        unsigned long long cw0 = 0ull, cw1 = 0ull;
#pragma unroll
        for (int w2 = 0; w2 < 8; ++w2) {
            if (w2 == wt) { cw0 = c0[w2]; cw1 = c1[w2]; }
        }
        bool u0 = (((cw0 >> sb) & 1ull) != 0ull) || (tid == t);
        bool u1 = (((cw1 >> sb) & 1ull) != 0ull) || (a1 == t);
        unsigned long long m0 = u0 ? ~0ull : 0ull;
        unsigned long long m1 = u1 ? ~0ull : 0ull;

        unsigned long long chg0 = 0ull, chg1 = 0ull;
#pragma unroll
        for (int w2 = 0; w2 < 8; ++w2) {
            unsigned long long n0 = cvAll[w2] & m0 & ~c0[w2];
            unsigned long long n1 = cvAll[w2] & m1 & ~c1[w2];
            chg0 |= n0; c0[w2] |= n0;
            chg1 |= n1; c1[w2] |= n1;
        }
        if (chg0) {
#pragma unroll
            for (int w2 = 0; w2 < 8; ++w2) colT[tid * CSTR + w2] = c0[w2];
        }
        if (chg1) {
#pragma unroll
            for (int w2 = 0; w2 < 8; ++w2) colT[a1 * CSTR + w2] = c1[w2];
        }
        __syncthreads();
    }

    // ---- ballot transpose: colT (shared) -> row-major g_mask32 ----
    int warpId = tid >> 5;
    for (int tile = warpId; tile < 128; tile += 8) {
        int cg = tile & 15;          // column group (32 cols)
        int wg = tile >> 4;          // word group (64 rows)
        unsigned long long x = colT[(cg * 32 + lane) * CSTR + wg];
#pragma unroll
        for (int k = 0; k < 64; ++k) {
            unsigned bal = __ballot_sync(0xFFFFFFFFu,
                                         (unsigned)((x >> k) & 1ull));
            if (lane == (k & 31)) g_mask32[b][wg * 64 + k][cg] = bal;
        }
    }
}

// ---------------- expand bool bitsets to float output regions (vectorized) -------
__global__ void k_expand(float* __restrict__ out) {
    int n = blockIdx.x * blockDim.x + threadIdx.x;   // over BSS/4
    if (n >= BSS / 4) return;
    int c4  = (n & 127) * 4;
    int mid = (n >> 7) & 511;
    int b   = n >> 16;

    unsigned long long selw = g_sel[mid][b][c4 >> 6];
    unsigned         mw   = g_mask32[b][mid][c4 >> 5];
    int shs = c4 & 63;
    int shm = c4 & 31;

    float4 z = make_float4(0.f, 0.f, 0.f, 0.f);
    float4 sv = make_float4((float)((selw >> shs) & 1ull),
                            (float)((selw >> (shs + 1)) & 1ull),
                            (float)((selw >> (shs + 2)) & 1ull),
                            (float)((selw >> (shs + 3)) & 1ull));
    float4 mv = make_float4((float)((mw >> shm) & 1u),
                            (float)((mw >> (shm + 1)) & 1u),
                            (float)((mw >> (shm + 2)) & 1u),
                            (float)((mw >> (shm + 3)) & 1u));

    *reinterpret_cast<float4*>(out + BSS + (size_t)n * 4)     = z;
    *reinterpret_cast<float4*>(out + 2 * BSS + (size_t)n * 4) = sv;
    *reinterpret_cast<float4*>(out + 3 * BSS + (size_t)n * 4) = mv;
}

// ---------------- launch ----------------
extern "C" void kernel_launch(void* const* d_in, const int* in_sizes, int n_in,
                              void* d_out, int out_size) {
    const float* inp  = (const float*)d_in[0];   // (B, F, S)
    const float* emb  = (const float*)d_in[1];   // (F, E)
    const float* W    = (const float*)d_in[2];   // (S, H, S)
    const float* bias = (const float*)d_in[3];   // (S, S)
    float* out = (float*)d_out;

    dim3 g1(4, 8, KSPLIT);
    k_gemm1<<<g1, 256>>>(inp, emb);                   // 1
    k_probs<<<512, 256>>>(W, bias, out);              // 2
    k_topk_sample<<<512, 256>>>(out);                 // 3
    k_scan<<<B, 256>>>();                             // 4  <- profiled slot
    k_expand<<<(BSS / 4 + 255) / 256, 256>>>(out);    // 5
}

// round 17
// speedup vs baseline: 1.0045x; 1.0045x over previous
#include <cuda_runtime.h>
#include <cstdint>

#define B 8
#define F 4000
#define S 512
#define E 128
#define H 128

#define SSQ   (S * S)          // 262144
#define BSS   (B * S * S)      // 2097152
#define BSE   (B * S * E)      // 524288

#define KSPLIT 8
#define KCH    (F / KSPLIT)    // 500
#define KB     20              // 25 chunks per block

#define CSTR  9                // padded u64 stride per column (bank-conflict fix)

// ---------------- device scratch (no allocations allowed) ----------------
__device__ float               g_partial[KSPLIT][BSE];   // split-K partials (16 MB)
__device__ unsigned short      g_cand[S][B][8];          // sampled top-8 positions (0xFFFF = no)
__device__ unsigned long long  g_sel[S][B][8];           // final samp per step (prev_idxs)
__device__ unsigned           g_mask32[B][S][16];        // final mask, row-major u32 words

// ---------------- threefry2x32 (exact JAX semantics) ----------------
__device__ __forceinline__ unsigned rotl32(unsigned v, int d) {
    return (v << d) | (v >> (32 - d));
}

__device__ __forceinline__ void threefry2x32(unsigned k0, unsigned k1,
                                             unsigned x0, unsigned x1,
                                             unsigned& o0, unsigned& o1) {
    unsigned ks0 = k0, ks1 = k1, ks2 = k0 ^ k1 ^ 0x1BD11BDAu;
    x0 += ks0; x1 += ks1;
#define TF_RND(r) { x0 += x1; x1 = rotl32(x1, r); x1 ^= x0; }
    TF_RND(13) TF_RND(15) TF_RND(26) TF_RND(6)
    x0 += ks1; x1 += ks2 + 1u;
    TF_RND(17) TF_RND(29) TF_RND(16) TF_RND(24)
    x0 += ks2; x1 += ks0 + 2u;
    TF_RND(13) TF_RND(15) TF_RND(26) TF_RND(6)
    x0 += ks0; x1 += ks1 + 3u;
    TF_RND(17) TF_RND(29) TF_RND(16) TF_RND(24)
    x0 += ks1; x1 += ks2 + 4u;
    TF_RND(13) TF_RND(15) TF_RND(26) TF_RND(6)
    x0 += ks2; x1 += ks0 + 5u;
#undef TF_RND
    o0 = x0; o1 = x1;
}

// ---------------- GEMM1: pre-tanh embedded, split-K, scalar FFMA ----------------
__global__ __launch_bounds__(256, 2)
void k_gemm1(const float* __restrict__ inp, const float* __restrict__ emb) {
    int stile = blockIdx.x;
    int b     = blockIdx.y;
    int ks    = blockIdx.z;
    int t     = threadIdx.x;

    __shared__ float As[KB][128];
    __shared__ float Bs[KB][128];

    int s0 = stile * 128;
    int f0 = ks * KCH;
    int tx = t & 15;
    int ty = t >> 4;

    float acc[8][8];
#pragma unroll
    for (int i = 0; i < 8; ++i)
#pragma unroll
        for (int j = 0; j < 8; ++j) acc[i][j] = 0.f;

    const float* inp_b = inp + (size_t)b * F * S + s0;

    for (int kb = 0; kb < KCH; kb += KB) {
#pragma unroll
        for (int p = 0; p < 10; ++p) {
            int idx = t + 256 * p;
            int row = idx >> 7, col = idx & 127;
            As[row][col] = inp_b[(size_t)(f0 + kb + row) * S + col];
            Bs[row][col] = emb[(size_t)(f0 + kb + row) * E + col];
        }
        __syncthreads();

#pragma unroll
        for (int k = 0; k < KB; ++k) {
            float4 a0 = *reinterpret_cast<const float4*>(&As[k][ty * 8]);
            float4 a1 = *reinterpret_cast<const float4*>(&As[k][ty * 8 + 4]);
            float4 b0 = *reinterpret_cast<const float4*>(&Bs[k][tx * 8]);
            float4 b1 = *reinterpret_cast<const float4*>(&Bs[k][tx * 8 + 4]);
            float av[8] = {a0.x, a0.y, a0.z, a0.w, a1.x, a1.y, a1.z, a1.w};
            float bv[8] = {b0.x, b0.y, b0.z, b0.w, b1.x, b1.y, b1.z, b1.w};
#pragma unroll
            for (int i = 0; i < 8; ++i)
#pragma unroll
                for (int j = 0; j < 8; ++j)
                    acc[i][j] = fmaf(av[i], bv[j], acc[i][j]);
        }
        __syncthreads();
    }

#pragma unroll
    for (int i = 0; i < 8; ++i) {
        float* dst = &g_partial[ks][(size_t)(b * S + s0 + ty * 8 + i) * E + tx * 8];
        *reinterpret_cast<float4*>(dst) =
            make_float4(acc[i][0], acc[i][1], acc[i][2], acc[i][3]);
        *reinterpret_cast<float4*>(dst + 4) =
            make_float4(acc[i][4], acc[i][5], acc[i][6], acc[i][7]);
    }
}

// ---------------- GEMM2 + inline split-K reduce + tanh + sigmoid + clip ---------
__global__ __launch_bounds__(256, 4)
void k_probs(const float* __restrict__ W, const float* __restrict__ bias,
             float* __restrict__ out) {
    int i  = blockIdx.x;
    int t  = threadIdx.x;
    int oq = t & 127;
    int hh = t >> 7;

    __shared__ float es[H][8];
    __shared__ float red[32][128];

#pragma unroll
    for (int p = 0; p < 4; ++p) {
        int idx = t + 256 * p;
        int bb = idx >> 7;
        int h  = idx & 127;
        float ssum = 0.f;
#pragma unroll
        for (int k = 0; k < KSPLIT; ++k)
            ssum += g_partial[k][(size_t)(bb * S + i) * H + h];
        es[h][bb] = tanhf(ssum);
    }
    __syncthreads();

    int o = oq * 4;
    float acc[8][4];
#pragma unroll
    for (int bb = 0; bb < 8; ++bb)
#pragma unroll
        for (int j = 0; j < 4; ++j) acc[bb][j] = 0.f;

    const float* Wp = W + (size_t)i * H * S + (size_t)(hh * 64) * S + o;
#pragma unroll 8
    for (int h = 0; h < 64; ++h) {
        float4 w4 = *reinterpret_cast<const float4*>(Wp + (size_t)h * S);
        float4 eA = *reinterpret_cast<const float4*>(&es[hh * 64 + h][0]);
        float4 eB = *reinterpret_cast<const float4*>(&es[hh * 64 + h][4]);
        float ev[8] = {eA.x, eA.y, eA.z, eA.w, eB.x, eB.y, eB.z, eB.w};
#pragma unroll
        for (int bb = 0; bb < 8; ++bb) {
            acc[bb][0] = fmaf(w4.x, ev[bb], acc[bb][0]);
            acc[bb][1] = fmaf(w4.y, ev[bb], acc[bb][1]);
            acc[bb][2] = fmaf(w4.z, ev[bb], acc[bb][2]);
            acc[bb][3] = fmaf(w4.w, ev[bb], acc[bb][3]);
        }
    }

    if (hh == 1) {
#pragma unroll
        for (int bb = 0; bb < 8; ++bb)
#pragma unroll
            for (int j = 0; j < 4; ++j)
                red[bb * 4 + j][oq] = acc[bb][j];
    }
    __syncthreads();

    if (hh == 0) {
        float4 bi4 = *reinterpret_cast<const float4*>(bias + (size_t)i * S + o);
        float bv[4] = {bi4.x, bi4.y, bi4.z, bi4.w};
#pragma unroll
        for (int bb = 0; bb < 8; ++bb) {
            float v[4];
#pragma unroll
            for (int j = 0; j < 4; ++j) {
                float x = acc[bb][j] + red[bb * 4 + j][oq] + bv[j];
                float p = 1.0f / (1.0f + expf(-x));
                v[j] = fminf(fmaxf(p, 1e-4f), 0.9999f);
            }
            *reinterpret_cast<float4*>(out + (size_t)(bb * S + i) * S + o) =
                make_float4(v[0], v[1], v[2], v[3]);
        }
    }
}

// ---------------- fused top-8 + bernoulli -> candidate position list ------------
__global__ void k_topk_sample(const float* __restrict__ probs) {
    int warp = blockIdx.x * (blockDim.x >> 5) + (threadIdx.x >> 5);  // 0..4095
    int lane = threadIdx.x & 31;
    int b = warp >> 9;
    int t = warp & 511;
    const float* row = probs + (size_t)(b * S + t) * S;

    float v[16];
#pragma unroll
    for (int j = 0; j < 16; ++j) v[j] = row[lane + 32 * j];

    unsigned taken = 0;
    int my_s = 0;

#pragma unroll
    for (int r = 0; r < 8; ++r) {
        float bestv = -1e30f;
        int   besto = 1 << 30;
#pragma unroll
        for (int j = 0; j < 16; ++j) {
            if (!((taken >> j) & 1u)) {
                int o = lane + 32 * j;
                if (v[j] > bestv) { bestv = v[j]; besto = o; }
            }
        }
#pragma unroll
        for (int d = 16; d; d >>= 1) {
            float ov = __shfl_xor_sync(0xFFFFFFFFu, bestv, d);
            int   oo = __shfl_xor_sync(0xFFFFFFFFu, besto, d);
            if (ov > bestv || (ov == bestv && oo < besto)) { bestv = ov; besto = oo; }
        }
        if ((besto & 31) == lane) taken |= 1u << (besto >> 5);
        if (lane == r) my_s = besto;
    }

    if (lane < 8) {
        unsigned kk0, kk1;
        threefry2x32(0u, 42u, 0u, (unsigned)t, kk0, kk1);
        unsigned o0, o1;
        threefry2x32(kk0, kk1, 0u, (unsigned)(b * S + my_s), o0, o1);
        unsigned bits = o0 ^ o1;
        float u = __uint_as_float((bits >> 9) | 0x3f800000u) - 1.0f;
        float p = row[my_s];
        g_cand[t][b][lane] = (u < p) ? (unsigned short)my_s : (unsigned short)0xFFFF;
    }
}

// ---------------- scan v4d: COLUMN-ONLY + stride-9 padding + SINGLE barrier -----
// v4c (344us measured) with the mid-step barrier removed. The intra-step A/B race
// is benign: B only updates columns whose bit t was set pre-step (disjoint from
// kept candidates, whose reads matter); filtered candidates' racy reads are
// masked; the filter bit (bit t) is never modified within the step (col_vec
// cannot contain bit t by acyclicity); LDS.64 is tear-free; per-thread B writes
// are disjoint. The single end-of-step barrier orders B(t) before A(t+1).
__global__ __launch_bounds__(256, 1)
void k_scan() {
    int b    = blockIdx.x;
    int tid  = threadIdx.x;
    int lane = tid & 31;
    int w    = lane & 7;          // word this lane computes in Phase A
    int jg   = lane >> 3;         // candidate group: handles jg and jg+4

    __shared__ unsigned long long colT[S * CSTR];  // 36.9KB column-major mask (padded)
    __shared__ ulonglong2         candS[S];        // 8KB candidate lists

    for (int i = tid; i < S * CSTR; i += 256) colT[i] = 0ull;
    for (int i = tid; i < S; i += 256)
        candS[i] = *reinterpret_cast<const ulonglong2*>(&g_cand[i][b][0]);

    unsigned long long c0[8] = {0,0,0,0,0,0,0,0};  // col tid (register mirror)
    unsigned long long c1[8] = {0,0,0,0,0,0,0,0};  // col tid+256
    __syncthreads();

    int a1 = tid + 256;

    for (int t = 0; t < S; ++t) {
        int wt = t >> 6;
        int sb = t & 63;

        // ---- Phase A (replicated in every warp; reads only) ----
        ulonglong2 cd = candS[t];
        int cA = (int)((cd.x >> (16 * jg)) & 0xFFFFull);
        int cB = (int)((cd.y >> (16 * jg)) & 0xFFFFull);

        unsigned long long anc = 0ull, smp = 0ull;
        {
            bool valid = (cA < S) && (cA != t);
            int ci = valid ? cA : 0;
            unsigned long long fw = colT[ci * CSTR + wt];   // filter: bit t (stable)
            unsigned long long cv = colT[ci * CSTR + w];    // anc contribution
            bool keep = valid && !((fw >> sb) & 1ull);
            if (keep) {
                anc |= cv;
                if ((ci >> 6) == w) smp |= 1ull << (ci & 63);
            }
        }
        {
            bool valid = (cB < S) && (cB != t);
            int ci = valid ? cB : 0;
            unsigned long long fw = colT[ci * CSTR + wt];
            unsigned long long cv = colT[ci * CSTR + w];
            bool keep = valid && !((fw >> sb) & 1ull);
            if (keep) {
                anc |= cv;
                if ((ci >> 6) == w) smp |= 1ull << (ci & 63);
            }
        }

        // reduce across the 4 candidate groups (lanes w, w+8, w+16, w+24)
        anc |= __shfl_xor_sync(0xFFFFFFFFu, anc, 8);
        anc |= __shfl_xor_sync(0xFFFFFFFFu, anc, 16);
        smp |= __shfl_xor_sync(0xFFFFFFFFu, smp, 8);
        smp |= __shfl_xor_sync(0xFFFFFFFFu, smp, 16);

        unsigned long long cvw = colT[t * CSTR + w] | smp | anc;  // col_vec word w

        unsigned long long cvAll[8];
#pragma unroll
        for (int w2 = 0; w2 < 8; ++w2)
            cvAll[w2] = __shfl_sync(0xFFFFFFFFu, cvw, w2);

        if (tid < 8) g_sel[t][b][tid] = smp;   // lanes 0..7 hold words 0..7

        // ---- Phase B: column updates only (no mid barrier; race proven benign) --
        unsigned long long cw0 = 0ull, cw1 = 0ull;
#pragma unroll
        for (int w2 = 0; w2 < 8; ++w2) {
            if (w2 == wt) { cw0 = c0[w2]; cw1 = c1[w2]; }
        }
        bool u0 = (((cw0 >> sb) & 1ull) != 0ull) || (tid == t);
        bool u1 = (((cw1 >> sb) & 1ull) != 0ull) || (a1 == t);
        unsigned long long m0 = u0 ? ~0ull : 0ull;
        unsigned long long m1 = u1 ? ~0ull : 0ull;

        unsigned long long chg0 = 0ull, chg1 = 0ull;
#pragma unroll
        for (int w2 = 0; w2 < 8; ++w2) {
            unsigned long long n0 = cvAll[w2] & m0 & ~c0[w2];
            unsigned long long n1 = cvAll[w2] & m1 & ~c1[w2];
            chg0 |= n0; c0[w2] |= n0;
            chg1 |= n1; c1[w2] |= n1;
        }
        if (chg0) {
#pragma unroll
            for (int w2 = 0; w2 < 8; ++w2) colT[tid * CSTR + w2] = c0[w2];
        }
        if (chg1) {
#pragma unroll
            for (int w2 = 0; w2 < 8; ++w2) colT[a1 * CSTR + w2] = c1[w2];
        }
        __syncthreads();   // orders B(t) before A(t+1)
    }

    // ---- ballot transpose: colT (shared) -> row-major g_mask32 ----
    int warpId = tid >> 5;
    for (int tile = warpId; tile < 128; tile += 8) {
        int cg = tile & 15;          // column group (32 cols)
        int wg = tile >> 4;          // word group (64 rows)
        unsigned long long x = colT[(cg * 32 + lane) * CSTR + wg];
#pragma unroll
        for (int k = 0; k < 64; ++k) {
            unsigned bal = __ballot_sync(0xFFFFFFFFu,
                                         (unsigned)((x >> k) & 1ull));
            if (lane == (k & 31)) g_mask32[b][wg * 64 + k][cg] = bal;
        }
    }
}

// ---------------- expand bool bitsets to float output regions (vectorized) -------
__global__ void k_expand(float* __restrict__ out) {
    int n = blockIdx.x * blockDim.x + threadIdx.x;   // over BSS/4
    if (n >= BSS / 4) return;
    int c4  = (n & 127) * 4;
    int mid = (n >> 7) & 511;
    int b   = n >> 16;

    unsigned long long selw = g_sel[mid][b][c4 >> 6];
    unsigned         mw   = g_mask32[b][mid][c4 >> 5];
    int shs = c4 & 63;
    int shm = c4 & 31;

    float4 z = make_float4(0.f, 0.f, 0.f, 0.f);
    float4 sv = make_float4((float)((selw >> shs) & 1ull),
                            (float)((selw >> (shs + 1)) & 1ull),
                            (float)((selw >> (shs + 2)) & 1ull),
                            (float)((selw >> (shs + 3)) & 1ull));
    float4 mv = make_float4((float)((mw >> shm) & 1u),
                            (float)((mw >> (shm + 1)) & 1u),
                            (float)((mw >> (shm + 2)) & 1u),
                            (float)((mw >> (shm + 3)) & 1u));

    *reinterpret_cast<float4*>(out + BSS + (size_t)n * 4)     = z;
    *reinterpret_cast<float4*>(out + 2 * BSS + (size_t)n * 4) = sv;
    *reinterpret_cast<float4*>(out + 3 * BSS + (size_t)n * 4) = mv;
}

// ---------------- launch ----------------
extern "C" void kernel_launch(void* const* d_in, const int* in_sizes, int n_in,
                              void* d_out, int out_size) {
    const float* inp  = (const float*)d_in[0];   // (B, F, S)
    const float* emb  = (const float*)d_in[1];   // (F, E)
    const float* W    = (const float*)d_in[2];   // (S, H, S)
    const float* bias = (const float*)d_in[3];   // (S, S)
    float* out = (float*)d_out;

    dim3 g1(4, 8, KSPLIT);
    k_gemm1<<<g1, 256>>>(inp, emb);                   // 1
    k_probs<<<512, 256>>>(W, bias, out);              // 2
    k_topk_sample<<<512, 256>>>(out);                 // 3
    k_scan<<<B, 256>>>();                             // 4  <- profiled slot
    k_expand<<<(BSS / 4 + 255) / 256, 256>>>(out);    // 5
}